// round 4
// baseline (speedup 1.0000x reference)
#include <cuda_runtime.h>
#include <cuda_bf16.h>
#include <cstdint>

// ---------------------------------------------------------------------------
// 2-layer GCN:  out = GCN2(relu(GCN1(x)))
//   GCN(h) = D^-1/2 (A+I) D^-1/2 (h W) + b
// N = 100000 nodes, E = 1.6M edges, F: 64 -> 64 -> 32
// NOTE: edge_index materializes as int32 (JAX x64 disabled).
// ---------------------------------------------------------------------------

#define N_MAX 100000
#define E_MAX 1600000

// Scratch (allocation-free: __device__ globals)
__device__ float4 g_h1  [N_MAX * 16];   // h1  = x @ W1           [N,64]
__device__ float4 g_agg1[N_MAX * 16];   // agg of layer 1         [N,64]
__device__ float4 g_h2  [N_MAX * 8];    // h2  = relu(.) @ W2     [N,32]
__device__ float  g_norm[E_MAX];        // dis[src]*dis[dst]
__device__ float  g_deg [N_MAX];
__device__ float  g_dis [N_MAX];        // rsqrt(deg+1)

// Scalar reductions (no-return atomicAdd -> RED.ADD.F32). v4 red traps on sm_103a.
__device__ __forceinline__ void red_add_4x(float* p, float4 v) {
    atomicAdd(p + 0, v.x);
    atomicAdd(p + 1, v.y);
    atomicAdd(p + 2, v.z);
    atomicAdd(p + 3, v.w);
}

// --------------------------- graph preprocessing ---------------------------

__global__ void k_zero_deg(int n) {
    int i = blockIdx.x * 256 + threadIdx.x;
    if (i < n) g_deg[i] = 0.f;
}

__global__ void k_deg(const int* __restrict__ ei, int E) {
    int e = blockIdx.x * 256 + threadIdx.x;
    if (e >= E) return;
    atomicAdd(&g_deg[ei[E + e]], 1.0f);
}

__global__ void k_dis(int n) {
    int i = blockIdx.x * 256 + threadIdx.x;
    if (i < n) g_dis[i] = rsqrtf(g_deg[i] + 1.0f);
}

__global__ void k_norm(const int* __restrict__ ei, int E) {
    int e = blockIdx.x * 256 + threadIdx.x;
    if (e >= E) return;
    g_norm[e] = g_dis[ei[e]] * g_dis[ei[E + e]];
}

// ------------------------------- GEMM layer 1 -------------------------------
// h1 = x @ W1  (64x64); fused epilogue: agg1 = h1 * dis^2  (self-loop init)
// 16 nodes / block of 256; each thread = (node, 4-feature group).

__global__ void k_mm1(const float* __restrict__ x,
                      const float* __restrict__ W,
                      int n) {
    __shared__ float4 Ws[64 * 16];      // W1 as [k][fg] float4, 16 KB
    __shared__ float  xs[16][68];       // padded x tile
    int tid = threadIdx.x;
    const float4* W4 = (const float4*)W;
    for (int i = tid; i < 1024; i += 256) Ws[i] = W4[i];

    int node0 = blockIdx.x * 16;
    for (int i = tid; i < 1024; i += 256) {
        int r = i >> 6, c = i & 63;
        int node = node0 + r;
        xs[r][c] = (node < n) ? x[node * 64 + c] : 0.f;
    }
    __syncthreads();

    int nl = tid >> 4, fg = tid & 15;
    int node = node0 + nl;
    float4 acc = make_float4(0.f, 0.f, 0.f, 0.f);
#pragma unroll
    for (int k = 0; k < 64; k++) {
        float  xv = xs[nl][k];
        float4 w  = Ws[k * 16 + fg];
        acc.x += xv * w.x; acc.y += xv * w.y;
        acc.z += xv * w.z; acc.w += xv * w.w;
    }
    if (node < n) {
        float di = g_dis[node];
        float d2 = di * di;
        g_h1[node * 16 + fg] = acc;
        g_agg1[node * 16 + fg] =
            make_float4(acc.x * d2, acc.y * d2, acc.z * d2, acc.w * d2);
    }
}

// ---------------------------- edge scatter layer 1 --------------------------
// thread t -> (edge e = t/16, chunk c = t%16); coalesced 256B gather per edge.

__global__ void k_scatter1(const int* __restrict__ ei, int E) {
    int t = blockIdx.x * 256 + threadIdx.x;
    if (t >= E * 16) return;
    int e = t >> 4, c = t & 15;
    int s = ei[e];
    int d = ei[E + e];
    float nrm = g_norm[e];
    float4 v = g_h1[s * 16 + c];
    v.x *= nrm; v.y *= nrm; v.z *= nrm; v.w *= nrm;
    red_add_4x(((float*)g_agg1) + (size_t)d * 64 + c * 4, v);
}

// ------------------------------- GEMM layer 2 -------------------------------
// t = relu(agg1 + b1); h2 = t @ W2 (64x32);
// epilogue: d_out = h2*dis^2 + b2 (scatter2 then red.adds directly into d_out)
// 32 nodes / block of 256; thread = (node, 4-feature group of 8).

__global__ void k_mm2(const float* __restrict__ b1,
                      const float* __restrict__ W2,
                      const float* __restrict__ b2,
                      float* __restrict__ out,
                      int n) {
    __shared__ float4 Ws[64 * 8];       // W2 as [k][fg], 8 KB
    __shared__ float  ts[32][68];
    int tid = threadIdx.x;
    const float4* W4 = (const float4*)W2;
    for (int i = tid; i < 512; i += 256) Ws[i] = W4[i];

    int node0 = blockIdx.x * 32;
    const float* a1 = (const float*)g_agg1;
    for (int i = tid; i < 2048; i += 256) {
        int r = i >> 6, c = i & 63;
        int node = node0 + r;
        float v = 0.f;
        if (node < n) v = fmaxf(a1[(size_t)node * 64 + c] + __ldg(&b1[c]), 0.f);
        ts[r][c] = v;
    }
    __syncthreads();

    int nl = tid >> 3, fg = tid & 7;
    int node = node0 + nl;
    float4 acc = make_float4(0.f, 0.f, 0.f, 0.f);
#pragma unroll
    for (int k = 0; k < 64; k++) {
        float  xv = ts[nl][k];
        float4 w  = Ws[k * 8 + fg];
        acc.x += xv * w.x; acc.y += xv * w.y;
        acc.z += xv * w.z; acc.w += xv * w.w;
    }
    if (node < n) {
        float di = g_dis[node];
        float d2 = di * di;
        g_h2[node * 8 + fg] = acc;
        float4 bb = ((const float4*)b2)[fg];
        float4 o = make_float4(acc.x * d2 + bb.x, acc.y * d2 + bb.y,
                               acc.z * d2 + bb.z, acc.w * d2 + bb.w);
        ((float4*)out)[node * 8 + fg] = o;
    }
}

// ---------------------------- edge scatter layer 2 --------------------------

__global__ void k_scatter2(const int* __restrict__ ei,
                           float* __restrict__ out, int E) {
    int t = blockIdx.x * 256 + threadIdx.x;
    if (t >= E * 8) return;
    int e = t >> 3, c = t & 7;
    int s = ei[e];
    int d = ei[E + e];
    float nrm = g_norm[e];
    float4 v = g_h2[s * 8 + c];
    v.x *= nrm; v.y *= nrm; v.z *= nrm; v.w *= nrm;
    red_add_4x(out + (size_t)d * 32 + c * 4, v);
}

// ---------------------------------------------------------------------------

extern "C" void kernel_launch(void* const* d_in, const int* in_sizes, int n_in,
                              void* d_out, int out_size) {
    const float* x  = (const float*)d_in[0];
    const int*   ei = (const int*)d_in[1];     // int32! (JAX x64 disabled)
    const float* W1 = (const float*)d_in[2];
    const float* b1 = (const float*)d_in[3];
    const float* W2 = (const float*)d_in[4];
    const float* b2 = (const float*)d_in[5];
    float* out = (float*)d_out;

    int n = out_size / 32;
    int E = in_sizes[1] / 2;

    k_zero_deg<<<(n + 255) / 256, 256>>>(n);
    k_deg     <<<(E + 255) / 256, 256>>>(ei, E);
    k_dis     <<<(n + 255) / 256, 256>>>(n);
    k_norm    <<<(E + 255) / 256, 256>>>(ei, E);
    k_mm1     <<<(n + 15) / 16, 256>>>(x, W1, n);
    k_scatter1<<<(E * 16 + 255) / 256, 256>>>(ei, E);
    k_mm2     <<<(n + 31) / 32, 256>>>(b1, W2, b2, out, n);
    k_scatter2<<<(E * 8 + 255) / 256, 256>>>(ei, out, E);
}

// round 5
// speedup vs baseline: 2.0102x; 2.0102x over previous
#include <cuda_runtime.h>
#include <cuda_bf16.h>
#include <cstdint>

// ---------------------------------------------------------------------------
// 2-layer GCN:  out = GCN2(relu(GCN1(x)))
//   GCN(h) = D^-1/2 (A+I) D^-1/2 (h W) + b
// N = 100000 nodes, E = 1.6M edges, F: 64 -> 64 -> 32
// Strategy: counting-sort edges by dst (CSR), then pull-style aggregation
// with register accumulation -> zero float atomics.
// ---------------------------------------------------------------------------

#define N_MAX 100000
#define E_MAX 1600000
#define SCAN_B 128          // max #scan blocks (N_MAX/1024 = 98)

// Scratch (allocation-free: __device__ globals)
__device__ float4 g_h1  [N_MAX * 16];   // h1  = x @ W1            [N,64]
__device__ float4 g_agg1[N_MAX * 16];   // aggregated layer 1      [N,64]
__device__ float4 g_h2  [N_MAX * 8];    // h2  = relu(.) @ W2      [N,32]
__device__ int2   g_edge[E_MAX];        // dst-sorted (src, norm-bits)
__device__ int    g_cnt [N_MAX];        // in-degree (histogram)
__device__ int    g_row [N_MAX];        // CSR row start
__device__ int    g_fill[N_MAX];        // fill cursor for reorder
__device__ int    g_bsum[SCAN_B];
__device__ int    g_boff[SCAN_B];
__device__ float  g_dis [N_MAX];        // rsqrt(deg+1)

// --------------------------- histogram + scan -------------------------------

__global__ void k_zero_cnt(int n) {
    int i = blockIdx.x * 256 + threadIdx.x;
    if (i < n) g_cnt[i] = 0;
}

__global__ void k_hist(const int* __restrict__ ei, int E) {
    int e = blockIdx.x * 256 + threadIdx.x;
    if (e >= E) return;
    atomicAdd(&g_cnt[ei[E + e]], 1);
}

// Block sums of g_cnt in chunks of 1024.
__global__ void k_scanA(int n) {
    __shared__ int s[1024];
    int t = threadIdx.x;
    int i = blockIdx.x * 1024 + t;
    s[t] = (i < n) ? g_cnt[i] : 0;
    __syncthreads();
    for (int off = 512; off > 0; off >>= 1) {
        if (t < off) s[t] += s[t + off];
        __syncthreads();
    }
    if (t == 0) g_bsum[blockIdx.x] = s[0];
}

// Exclusive scan of block sums (single block, 128 threads).
__global__ void k_scanB(int nb) {
    __shared__ int s[SCAN_B];
    int t = threadIdx.x;
    int v = (t < nb) ? g_bsum[t] : 0;
    s[t] = v;
    __syncthreads();
    for (int off = 1; off < SCAN_B; off <<= 1) {
        int add = (t >= off) ? s[t - off] : 0;
        __syncthreads();
        s[t] += add;
        __syncthreads();
    }
    if (t < nb) g_boff[t] = s[t] - v;
}

// Per-chunk exclusive scan + row starts + fill cursors + dis.
__global__ void k_scanC(int n) {
    __shared__ int s[1024];
    int t = threadIdx.x;
    int i = blockIdx.x * 1024 + t;
    int v = (i < n) ? g_cnt[i] : 0;
    s[t] = v;
    __syncthreads();
    for (int off = 1; off < 1024; off <<= 1) {
        int add = (t >= off) ? s[t - off] : 0;
        __syncthreads();
        s[t] += add;
        __syncthreads();
    }
    if (i < n) {
        int start = g_boff[blockIdx.x] + s[t] - v;
        g_row[i]  = start;
        g_fill[i] = start;
        g_dis[i]  = rsqrtf((float)v + 1.0f);
    }
}

// Scatter edges into dst-sorted order; fold in norm = dis[src]*dis[dst].
__global__ void k_reorder(const int* __restrict__ ei, int E) {
    int e = blockIdx.x * 256 + threadIdx.x;
    if (e >= E) return;
    int s = ei[e];
    int d = ei[E + e];
    float nm = g_dis[s] * g_dis[d];
    int pos = atomicAdd(&g_fill[d], 1);
    g_edge[pos] = make_int2(s, __float_as_int(nm));
}

// ------------------------------- GEMM layer 1 -------------------------------
// h1 = x @ W1 (64x64). 16 nodes / 256-thread block; thread = (node, float4 col).

__global__ void k_mm1(const float* __restrict__ x,
                      const float* __restrict__ W,
                      int n) {
    __shared__ float4 Ws[64 * 16];
    __shared__ float  xs[16][68];
    int tid = threadIdx.x;
    const float4* W4 = (const float4*)W;
    for (int i = tid; i < 1024; i += 256) Ws[i] = W4[i];

    int node0 = blockIdx.x * 16;
    for (int i = tid; i < 1024; i += 256) {
        int r = i >> 6, c = i & 63;
        int node = node0 + r;
        xs[r][c] = (node < n) ? x[node * 64 + c] : 0.f;
    }
    __syncthreads();

    int nl = tid >> 4, fg = tid & 15;
    int node = node0 + nl;
    float4 acc = make_float4(0.f, 0.f, 0.f, 0.f);
#pragma unroll
    for (int k = 0; k < 64; k++) {
        float  xv = xs[nl][k];
        float4 w  = Ws[k * 16 + fg];
        acc.x += xv * w.x; acc.y += xv * w.y;
        acc.z += xv * w.z; acc.w += xv * w.w;
    }
    if (node < n) g_h1[node * 16 + fg] = acc;
}

// ---------------------------- aggregation layer 1 ---------------------------
// One warp per dst node. Lanes 0-15 handle edge j, lanes 16-31 edge j+1;
// lane's float4 column c = lane & 15. Register accumulate, shfl-reduce, store.

__global__ void k_agg1(int n) {
    int w = (blockIdx.x * 256 + threadIdx.x) >> 5;   // node (uniform per warp)
    if (w >= n) return;
    int lane = threadIdx.x & 31;
    int c    = lane & 15;
    int half = lane >> 4;

    int start = g_row[w];
    int cnt   = g_cnt[w];
    float4 acc = make_float4(0.f, 0.f, 0.f, 0.f);

#pragma unroll 2
    for (int j = half; j < cnt; j += 2) {
        int2  r  = g_edge[start + j];
        float nm = __int_as_float(r.y);
        float4 a = g_h1[r.x * 16 + c];
        acc.x += nm * a.x; acc.y += nm * a.y;
        acc.z += nm * a.z; acc.w += nm * a.w;
    }
    acc.x += __shfl_xor_sync(0xffffffff, acc.x, 16);
    acc.y += __shfl_xor_sync(0xffffffff, acc.y, 16);
    acc.z += __shfl_xor_sync(0xffffffff, acc.z, 16);
    acc.w += __shfl_xor_sync(0xffffffff, acc.w, 16);

    if (half == 0) {
        float di = g_dis[w];
        float d2 = di * di;
        float4 h = g_h1[w * 16 + c];
        acc.x += d2 * h.x; acc.y += d2 * h.y;
        acc.z += d2 * h.z; acc.w += d2 * h.w;
        g_agg1[w * 16 + c] = acc;
    }
}

// ------------------------------- GEMM layer 2 -------------------------------
// t = relu(agg1 + b1); h2 = t @ W2 (64x32). 32 nodes / 256-thread block.

__global__ void k_mm2(const float* __restrict__ b1,
                      const float* __restrict__ W2,
                      int n) {
    __shared__ float4 Ws[64 * 8];
    __shared__ float  ts[32][68];
    int tid = threadIdx.x;
    const float4* W4 = (const float4*)W2;
    for (int i = tid; i < 512; i += 256) Ws[i] = W4[i];

    int node0 = blockIdx.x * 32;
    const float* a1 = (const float*)g_agg1;
    for (int i = tid; i < 2048; i += 256) {
        int r = i >> 6, c = i & 63;
        int node = node0 + r;
        float v = 0.f;
        if (node < n) v = fmaxf(a1[(size_t)node * 64 + c] + __ldg(&b1[c]), 0.f);
        ts[r][c] = v;
    }
    __syncthreads();

    int nl = tid >> 3, fg = tid & 7;
    int node = node0 + nl;
    float4 acc = make_float4(0.f, 0.f, 0.f, 0.f);
#pragma unroll
    for (int k = 0; k < 64; k++) {
        float  xv = ts[nl][k];
        float4 w  = Ws[k * 8 + fg];
        acc.x += xv * w.x; acc.y += xv * w.y;
        acc.z += xv * w.z; acc.w += xv * w.w;
    }
    if (node < n) g_h2[node * 8 + fg] = acc;
}

// ---------------------------- aggregation layer 2 ---------------------------
// One warp per dst node; 8 lanes per edge (c = lane&7), 4 edges in flight.
// Writes d_out = sum + h2*dis^2 + b2 directly.

__global__ void k_agg2(const float* __restrict__ b2,
                       float* __restrict__ out, int n) {
    int w = (blockIdx.x * 256 + threadIdx.x) >> 5;
    if (w >= n) return;
    int lane = threadIdx.x & 31;
    int c    = lane & 7;
    int sub  = lane >> 3;   // 0..3

    int start = g_row[w];
    int cnt   = g_cnt[w];
    float4 acc = make_float4(0.f, 0.f, 0.f, 0.f);

#pragma unroll 2
    for (int j = sub; j < cnt; j += 4) {
        int2  r  = g_edge[start + j];
        float nm = __int_as_float(r.y);
        float4 a = g_h2[r.x * 8 + c];
        acc.x += nm * a.x; acc.y += nm * a.y;
        acc.z += nm * a.z; acc.w += nm * a.w;
    }
    acc.x += __shfl_xor_sync(0xffffffff, acc.x, 16);
    acc.y += __shfl_xor_sync(0xffffffff, acc.y, 16);
    acc.z += __shfl_xor_sync(0xffffffff, acc.z, 16);
    acc.w += __shfl_xor_sync(0xffffffff, acc.w, 16);
    acc.x += __shfl_xor_sync(0xffffffff, acc.x, 8);
    acc.y += __shfl_xor_sync(0xffffffff, acc.y, 8);
    acc.z += __shfl_xor_sync(0xffffffff, acc.z, 8);
    acc.w += __shfl_xor_sync(0xffffffff, acc.w, 8);

    if (sub == 0) {
        float di = g_dis[w];
        float d2 = di * di;
        float4 h  = g_h2[w * 8 + c];
        float4 bb = ((const float4*)b2)[c];
        acc.x += d2 * h.x + bb.x; acc.y += d2 * h.y + bb.y;
        acc.z += d2 * h.z + bb.z; acc.w += d2 * h.w + bb.w;
        ((float4*)out)[w * 8 + c] = acc;
    }
}

// ---------------------------------------------------------------------------

extern "C" void kernel_launch(void* const* d_in, const int* in_sizes, int n_in,
                              void* d_out, int out_size) {
    const float* x  = (const float*)d_in[0];
    const int*   ei = (const int*)d_in[1];     // int32 (JAX x64 disabled)
    const float* W1 = (const float*)d_in[2];
    const float* b1 = (const float*)d_in[3];
    const float* W2 = (const float*)d_in[4];
    const float* b2 = (const float*)d_in[5];
    float* out = (float*)d_out;

    int n = out_size / 32;
    int E = in_sizes[1] / 2;
    int nb = (n + 1023) / 1024;                // scan blocks (<= 128)

    k_zero_cnt<<<(n + 255) / 256, 256>>>(n);
    k_hist    <<<(E + 255) / 256, 256>>>(ei, E);
    k_scanA   <<<nb, 1024>>>(n);
    k_scanB   <<<1, SCAN_B>>>(nb);
    k_scanC   <<<nb, 1024>>>(n);
    k_reorder <<<(E + 255) / 256, 256>>>(ei, E);
    k_mm1     <<<(n + 15) / 16, 256>>>(x, W1, n);
    k_agg1    <<<(n * 32 + 255) / 256, 256>>>(n);
    k_mm2     <<<(n + 31) / 32, 256>>>(b1, W2, n);
    k_agg2    <<<(n * 32 + 255) / 256, 256>>>(b2, out, n);
}